// round 15
// baseline (speedup 1.0000x reference)
#include <cuda_runtime.h>
#include <cuda_fp16.h>

#define NN 102400
#define EE 1638400
#define SLOTS 64                  // fixed CSR row capacity (P(overflow) ~ 1e-20)
#define GG 256
#define FULL 0xffffffffu
#define NEG_INF __int_as_float(0xff800000)
#define LOG2E 1.4426950408889634f

// ---------------- scratch (device globals; no allocation) ----------------
// Invariant: g_pos and g_pool are ZERO at entry of every kernel_launch call.
// Rows NN of g_h1h / g_h2h are NEVER written -> remain zero (dummy pad node).
// All logits are stored PRE-SCALED by log2(e).
__device__ __align__(16) __half g_h1h[(NN + 1) * 128];
__device__ __align__(16) float  g_als1[(NN + 1) * 4];
__device__ __align__(16) float  g_ald1[NN * 4];
__device__ __align__(16) __half g_h2h[(NN + 1) * 32];
__device__ __align__(16) float  g_als2[NN + 1];
__device__ __align__(16) float  g_ald2[NN];
__device__ __align__(16) int    g_pos[NN];
__device__ __align__(16) int    g_len[NN];
__device__ __align__(16) int    g_csr[NN * SLOTS];
__device__ __align__(16) float  g_pool[GG * 32];
__device__ __align__(16) __half g_w1t[128 * 64];   // W1^T fp16: [col][k]
__device__ __align__(16) __half g_w2t[32 * 128];   // W2^T fp16: [col][k]

__device__ __forceinline__ float eluf(float v) {
    return (v > 0.f) ? v : (__expf(v) - 1.f);
}
__device__ __forceinline__ unsigned int packh2(float2 v) {
    __half2 h = __floats2half2_rn(v.x, v.y);
    return *(unsigned int*)&h;
}
__device__ __forceinline__ void mma16816(float* c,
                                         unsigned a0, unsigned a1, unsigned a2, unsigned a3,
                                         unsigned b0, unsigned b1) {
    asm volatile("mma.sync.aligned.m16n8k16.row.col.f32.f16.f16.f32 "
                 "{%0,%1,%2,%3}, {%4,%5,%6,%7}, {%8,%9}, {%0,%1,%2,%3};"
                 : "+f"(c[0]), "+f"(c[1]), "+f"(c[2]), "+f"(c[3])
                 : "r"(a0), "r"(a1), "r"(a2), "r"(a3), "r"(b0), "r"(b1));
}
__device__ __forceinline__ __half2 h2shfl_xor(__half2 v, int off) {
    unsigned u = __shfl_xor_sync(FULL, *(unsigned*)&v, off);
    return *(__half2*)&u;
}
// f is (logit sum) pre-scaled by log2e; returns exp(lrelu(e)); 0 for f = -inf
__device__ __forceinline__ float wexp2(float f) {
    float m = fmaxf(f, 0.2f * f);
    float r;
    asm("ex2.approx.f32 %0, %1;" : "=f"(r) : "f"(m));
    return r;
}

// ---------------- launch 0: bucket scatter + W1T/W2T conversion ----------------
#define SCAT_BLOCKS 2000           // (EE/4 + NN) / 256
__global__ void __launch_bounds__(256) k_scatter(
        const int* __restrict__ ei,
        const float* __restrict__ W1,
        const float* __restrict__ W2) {
    int b = blockIdx.x;
    if (b < SCAT_BLOCKS) {
        int t = b * 256 + threadIdx.x;         // < 512000 = EE/4 + NN
        const int Q = EE / 4;
        if (t < Q) {
            int4 s4 = ((const int4*)ei)[t];
            int4 d4 = ((const int4*)(ei + EE))[t];
            int p;
            p = atomicAdd(&g_pos[d4.x], 1); g_csr[(d4.x << 6) + p] = s4.x;
            p = atomicAdd(&g_pos[d4.y], 1); g_csr[(d4.y << 6) + p] = s4.y;
            p = atomicAdd(&g_pos[d4.z], 1); g_csr[(d4.z << 6) + p] = s4.z;
            p = atomicAdd(&g_pos[d4.w], 1); g_csr[(d4.w << 6) + p] = s4.w;
        } else {
            int n = t - Q;                      // self loop
            int p = atomicAdd(&g_pos[n], 1);
            g_csr[(n << 6) + p] = n;
        }
        return;
    }
    int idx = (b - SCAT_BLOCKS) * 256 + threadIdx.x;   // 0..12287
    if (idx < 8192) {
        int n = idx >> 6, k = idx & 63;
        g_w1t[idx] = __float2half(W1[k * 128 + n]);
    } else {
        int j = idx - 8192;                    // 0..4095
        int col = j >> 7, k = j & 127;
        g_w2t[j] = __float2half(W2[k * 32 + col]);
    }
    if (idx == 0) {
        g_als1[4 * NN]     = NEG_INF;
        g_als1[4 * NN + 1] = NEG_INF;
        g_als1[4 * NN + 2] = NEG_INF;
        g_als1[4 * NN + 3] = NEG_INF;
        g_als2[NN] = NEG_INF;
    }
}

// ---------------- launch 1: tensor-core gemm1 (blocks 0..6399) + row pad (blocks 6400..6799) ----------------
#define GEMM1_BLOCKS (NN / 16)
__global__ void __launch_bounds__(128) k_gemm1pad(
        const float* __restrict__ x,
        const float* __restrict__ a_src1,
        const float* __restrict__ a_dst1) {
    if (blockIdx.x >= GEMM1_BLOCKS) {
        // pad rows to multiple of 4; store len; reset g_pos
        int n = (blockIdx.x - GEMM1_BLOCKS) * 128 + threadIdx.x;   // 400 blocks x 128... need 102400/128 = 800
        // handle 2 nodes per thread to cover NN with 400 blocks of 128
        for (int r = 0; r < 2; r++) {
            int nn = n * 2 + r;
            if (nn < NN) {
                int p = g_pos[nn];
                g_pos[nn] = 0;
                int end = (p + 3) & ~3;
                g_len[nn] = end;
                int base = nn << 6;
                for (int i = p; i < end; i++) g_csr[base + i] = NN;
            }
        }
        return;
    }
    int n0 = blockIdx.x * 16;
    int w = threadIdx.x >> 5;
    int l = threadIdx.x & 31;
    int g = l >> 2, tg = l & 3;

    const float2* xg  = (const float2*)(x + (n0 + g) * 64);
    const float2* xg8 = (const float2*)(x + (n0 + g + 8) * 64);

    float acc[4][4];
#pragma unroll
    for (int t = 0; t < 4; t++)
#pragma unroll
        for (int i = 0; i < 4; i++) acc[t][i] = 0.f;

#pragma unroll
    for (int ks = 0; ks < 4; ks++) {
        unsigned a0 = packh2(xg [8 * ks + tg]);
        unsigned a1 = packh2(xg8[8 * ks + tg]);
        unsigned a2 = packh2(xg [8 * ks + tg + 4]);
        unsigned a3 = packh2(xg8[8 * ks + tg + 4]);
#pragma unroll
        for (int t = 0; t < 4; t++) {
            int col = 32 * w + 8 * t + g;
            unsigned b0 = *(const unsigned*)&g_w1t[col * 64 + 16 * ks + 2 * tg];
            unsigned b1 = *(const unsigned*)&g_w1t[col * 64 + 16 * ks + 2 * tg + 8];
            mma16816(acc[t], a0, a1, a2, a3, b0, b1);
        }
    }

    float psg = 0.f, psg8 = 0.f, pdg = 0.f, pdg8 = 0.f;
#pragma unroll
    for (int t = 0; t < 4; t++) {
        int c0 = 32 * w + 8 * t + 2 * tg;
        __half2 h01 = __floats2half2_rn(acc[t][0], acc[t][1]);
        __half2 h23 = __floats2half2_rn(acc[t][2], acc[t][3]);
        *(__half2*)&g_h1h[(n0 + g) * 128 + c0]     = h01;
        *(__half2*)&g_h1h[(n0 + g + 8) * 128 + c0] = h23;
        float as0 = a_src1[c0], as1 = a_src1[c0 + 1];
        float ad0 = a_dst1[c0], ad1 = a_dst1[c0 + 1];
        psg  += acc[t][0] * as0 + acc[t][1] * as1;
        psg8 += acc[t][2] * as0 + acc[t][3] * as1;
        pdg  += acc[t][0] * ad0 + acc[t][1] * ad1;
        pdg8 += acc[t][2] * ad0 + acc[t][3] * ad1;
    }
    psg  += __shfl_down_sync(FULL, psg, 2, 4);  psg  += __shfl_down_sync(FULL, psg, 1, 4);
    psg8 += __shfl_down_sync(FULL, psg8, 2, 4); psg8 += __shfl_down_sync(FULL, psg8, 1, 4);
    pdg  += __shfl_down_sync(FULL, pdg, 2, 4);  pdg  += __shfl_down_sync(FULL, pdg, 1, 4);
    pdg8 += __shfl_down_sync(FULL, pdg8, 2, 4); pdg8 += __shfl_down_sync(FULL, pdg8, 1, 4);
    if (tg == 0) {
        g_als1[(n0 + g) * 4 + w]     = psg * LOG2E;
        g_als1[(n0 + g + 8) * 4 + w] = psg8 * LOG2E;
        g_ald1[(n0 + g) * 4 + w]     = pdg * LOG2E;
        g_ald1[(n0 + g + 8) * 4 + w] = pdg8 * LOG2E;
    }
}

// ---------------- launch 2: FUSED gather1 + normalize + ELU + tensor-core gemm2 + logits2 ----------------
// block = 512 thr = 16 warps = 16 nodes. Gather: warp-per-node (proven structure),
// act to SHARED. Epilogue: warps 0-3 run m16n8k16 gemm2 (warp w = 8 output cols).
__global__ void __launch_bounds__(512) k_edge1(const float* __restrict__ b1,
                                               const float* __restrict__ a2s,
                                               const float* __restrict__ a2d) {
    __shared__ __align__(16) __half act_s[16][128];
    __shared__ float ps_s[4][16];
    __shared__ float pd_s[4][16];

    int tid = threadIdx.x;
    int lane = tid & 31;
    int wid = tid >> 5;
    int d = (blockIdx.x << 4) + wid;
    int head = lane >> 3;

    const float2* h1v = (const float2*)g_h1h;

    float ald = g_ald1[4 * d + head];
    int beg = d << 6, end = beg + g_len[d];
    __half2 a01 = __float2half2_rn(0.f);
    __half2 a23 = __float2half2_rn(0.f);
    float den = 0.f;

    for (int j = beg; j < end; j += 4) {
        int4 s4 = *(const int4*)&g_csr[j];
        float l0 = g_als1[4 * s4.x + head];
        float l1 = g_als1[4 * s4.y + head];
        float l2 = g_als1[4 * s4.z + head];
        float l3 = g_als1[4 * s4.w + head];
        float2 r0 = h1v[(s4.x << 5) + lane];
        float2 r1 = h1v[(s4.y << 5) + lane];
        float2 r2 = h1v[(s4.z << 5) + lane];
        float2 r3 = h1v[(s4.w << 5) + lane];
        float w0 = wexp2(l0 + ald);
        float w1 = wexp2(l1 + ald);
        float w2 = wexp2(l2 + ald);
        float w3 = wexp2(l3 + ald);
        den += (w0 + w1) + (w2 + w3);
        __half2 h0 = __float2half2_rn(w0);
        __half2 h1w = __float2half2_rn(w1);
        __half2 h2w = __float2half2_rn(w2);
        __half2 h3w = __float2half2_rn(w3);
        a01 = __hfma2(*(__half2*)&r0.x, h0, a01);
        a23 = __hfma2(*(__half2*)&r0.y, h0, a23);
        a01 = __hfma2(*(__half2*)&r1.x, h1w, a01);
        a23 = __hfma2(*(__half2*)&r1.y, h1w, a23);
        a01 = __hfma2(*(__half2*)&r2.x, h2w, a01);
        a23 = __hfma2(*(__half2*)&r2.y, h2w, a23);
        a01 = __hfma2(*(__half2*)&r3.x, h3w, a01);
        a23 = __hfma2(*(__half2*)&r3.y, h3w, a23);
    }

    float inv = 1.f / den;
    float4 bb = *(const float4*)&b1[lane * 4];
    float2 f01 = __half22float2(a01);
    float2 f23 = __half22float2(a23);
    __half2 p0 = __floats2half2_rn(eluf(f01.x * inv + bb.x), eluf(f01.y * inv + bb.y));
    __half2 p1 = __floats2half2_rn(eluf(f23.x * inv + bb.z), eluf(f23.y * inv + bb.w));
    uint2 st;
    st.x = *(unsigned int*)&p0;
    st.y = *(unsigned int*)&p1;
    *(uint2*)&act_s[wid][lane * 4] = st;
    __syncthreads();

    // ---- epilogue: gemm2 for these 16 nodes. warp t = wid (0..3) owns cols [8t, 8t+8).
    if (wid < 4) {
        int t = wid;
        int g = lane >> 2, tg = lane & 3;
        const __half* act0 = act_s[g];
        const __half* act8 = act_s[g + 8];
        int col = 8 * t + g;

        float acc[4] = {0.f, 0.f, 0.f, 0.f};
#pragma unroll
        for (int ks = 0; ks < 8; ks++) {
            unsigned a0 = *(const unsigned*)&act0[16 * ks + 2 * tg];
            unsigned a1 = *(const unsigned*)&act8[16 * ks + 2 * tg];
            unsigned a2 = *(const unsigned*)&act0[16 * ks + 8 + 2 * tg];
            unsigned a3 = *(const unsigned*)&act8[16 * ks + 8 + 2 * tg];
            unsigned b0 = *(const unsigned*)&g_w2t[col * 128 + 16 * ks + 2 * tg];
            unsigned b1 = *(const unsigned*)&g_w2t[col * 128 + 16 * ks + 2 * tg + 8];
            mma16816(acc, a0, a1, a2, a3, b0, b1);
        }

        int n0 = blockIdx.x << 4;
        int c0 = 8 * t + 2 * tg;
        *(__half2*)&g_h2h[(n0 + g) * 32 + c0]     = __floats2half2_rn(acc[0], acc[1]);
        *(__half2*)&g_h2h[(n0 + g + 8) * 32 + c0] = __floats2half2_rn(acc[2], acc[3]);
        float as0 = a2s[c0], as1 = a2s[c0 + 1];
        float ad0 = a2d[c0], ad1 = a2d[c0 + 1];
        float psg  = acc[0] * as0 + acc[1] * as1;
        float psg8 = acc[2] * as0 + acc[3] * as1;
        float pdg  = acc[0] * ad0 + acc[1] * ad1;
        float pdg8 = acc[2] * ad0 + acc[3] * ad1;
        psg  += __shfl_down_sync(FULL, psg, 2, 4);  psg  += __shfl_down_sync(FULL, psg, 1, 4);
        psg8 += __shfl_down_sync(FULL, psg8, 2, 4); psg8 += __shfl_down_sync(FULL, psg8, 1, 4);
        pdg  += __shfl_down_sync(FULL, pdg, 2, 4);  pdg  += __shfl_down_sync(FULL, pdg, 1, 4);
        pdg8 += __shfl_down_sync(FULL, pdg8, 2, 4); pdg8 += __shfl_down_sync(FULL, pdg8, 1, 4);
        if (tg == 0) {
            ps_s[t][g]     = psg;
            ps_s[t][g + 8] = psg8;
            pd_s[t][g]     = pdg;
            pd_s[t][g + 8] = pdg8;
        }
    }
    __syncthreads();
    if (tid < 16) {
        int n = (blockIdx.x << 4) + tid;
        float ps = ps_s[0][tid] + ps_s[1][tid] + ps_s[2][tid] + ps_s[3][tid];
        float pd = pd_s[0][tid] + pd_s[1][tid] + pd_s[2][tid] + pd_s[3][tid];
        g_als2[n] = ps * LOG2E;
        g_ald2[n] = pd * LOG2E;
    }
}

// ---------------- launch 3 (PROFILED): gather2, branchless padded; pooled reduction ----------------
__global__ void __launch_bounds__(256) k_edge2(const float* __restrict__ b2) {
    int lane = threadIdx.x & 31;
    int d = (blockIdx.x << 3) + (threadIdx.x >> 5);
    int hw = lane >> 4;
    int c2 = (lane & 15) << 1;
    float ald = g_ald2[d];
    int beg = d << 6, end = beg + g_len[d];
    __half2 acc = __float2half2_rn(0.f);
    float den = 0.f;
    for (int j = beg; j < end; j += 4) {
        int s0 = g_csr[j + hw];
        int s1 = g_csr[j + 2 + hw];
        float l0 = g_als2[s0];
        float l1 = g_als2[s1];
        __half2 v0 = *(const __half2*)(g_h2h + s0 * 32 + c2);
        __half2 v1 = *(const __half2*)(g_h2h + s1 * 32 + c2);
        float w0 = wexp2(l0 + ald);
        float w1 = wexp2(l1 + ald);
        den += w0 + w1;
        acc = __hfma2(v0, __float2half2_rn(w0), acc);
        acc = __hfma2(v1, __float2half2_rn(w1), acc);
    }
    den += __shfl_xor_sync(FULL, den, 16);
    acc = __hadd2(acc, h2shfl_xor(acc, 16));
    if (hw == 0) {
        float inv = 1.f / den;
        float2 f = __half22float2(acc);
        float vx = eluf(f.x * inv + b2[c2]);
        float vy = eluf(f.y * inv + b2[c2 + 1]);
        int g = d / 400;
        atomicAdd(&g_pool[g * 32 + c2], vx);
        atomicAdd(&g_pool[g * 32 + c2 + 1], vy);
    }
}

// ---------------- launch 4: classifier MLP (resets g_pool) ----------------
__global__ void k_mlp(const float* __restrict__ clinical,
                      const float* __restrict__ Wc1,
                      const float* __restrict__ bc1,
                      const float* __restrict__ Wc2,
                      const float* __restrict__ bc2,
                      float* __restrict__ out) {
    int g = blockIdx.x;
    int t = threadIdx.x;
    __shared__ float sf[37];
    __shared__ float sz[16];
    if (t < 32) {
        sf[t] = g_pool[g * 32 + t] * (1.f / 400.f);
        g_pool[g * 32 + t] = 0.f;
    } else if (t < 37) {
        sf[t] = clinical[g * 5 + (t - 32)];
    }
    __syncthreads();
    if (t < 16) {
        float z = bc1[t];
#pragma unroll
        for (int i = 0; i < 37; i++) z += sf[i] * Wc1[i * 16 + t];
        sz[t] = eluf(z);
    }
    __syncthreads();
    if (t == 0) {
        float o = bc2[0];
#pragma unroll
        for (int j = 0; j < 16; j++) o += sz[j] * Wc2[j];
        out[g] = o;
    }
}

// ---------------- launch ----------------
extern "C" void kernel_launch(void* const* d_in, const int* in_sizes, int n_in,
                              void* d_out, int out_size) {
    const float* x        = (const float*)d_in[0];
    const int*   ei       = (const int*)d_in[1];
    const float* clinical = (const float*)d_in[3];
    const float* W1       = (const float*)d_in[4];
    const float* a_src1   = (const float*)d_in[5];
    const float* a_dst1   = (const float*)d_in[6];
    const float* b1       = (const float*)d_in[7];
    const float* W2       = (const float*)d_in[8];
    const float* a_src2   = (const float*)d_in[9];
    const float* a_dst2   = (const float*)d_in[10];
    const float* b2       = (const float*)d_in[11];
    const float* Wc1      = (const float*)d_in[12];
    const float* bc1      = (const float*)d_in[13];
    const float* Wc2      = (const float*)d_in[14];
    const float* bc2      = (const float*)d_in[15];
    float* out = (float*)d_out;

    k_scatter<<<SCAT_BLOCKS + 48, 256>>>(ei, W1, W2);
    k_gemm1pad<<<GEMM1_BLOCKS + NN / 256, 128>>>(x, a_src1, a_dst1);
    k_edge1<<<NN / 16, 512>>>(b1, a_src2, a_dst2);
    k_edge2<<<NN / 8, 256>>>(b2);                       // idx 3 -> profiled
    k_mlp<<<GG, 64>>>(clinical, Wc1, bc1, Wc2, bc2, out);
}

// round 16
// speedup vs baseline: 1.0603x; 1.0603x over previous
#include <cuda_runtime.h>
#include <cuda_fp16.h>

#define NN 102400
#define EE 1638400
#define SLOTS 64                  // fixed CSR row capacity (P(overflow) ~ 1e-15)
#define GG 256
#define FULL 0xffffffffu
#define NEG_INF __int_as_float(0xff800000)
#define LOG2E 1.4426950408889634f

// ---------------- scratch (device globals; no allocation) ----------------
// Invariant: g_pos and g_pool are ZERO at entry of every kernel_launch call.
// Rows NN of g_h1h / g_h2h are NEVER written -> remain zero (dummy pad node).
// All logits are stored PRE-SCALED by log2(e).
__device__ __align__(16) __half g_h1h[(NN + 1) * 128];
__device__ __align__(16) float  g_als1[(NN + 1) * 4];
__device__ __align__(16) float  g_ald1[NN * 4];
__device__ __align__(16) __half g_act[NN * 128];
__device__ __align__(16) __half g_h2h[(NN + 1) * 32];
__device__ __align__(16) float  g_als2[NN + 1];
__device__ __align__(16) float  g_ald2[NN];
__device__ __align__(16) int    g_pos[NN];
__device__ __align__(16) int    g_len[NN];
__device__ __align__(16) int    g_csr[NN * SLOTS];
__device__ __align__(16) float  g_pool[GG * 32];
__device__ __align__(16) __half g_w1t[128 * 64];   // W1^T fp16: [col][k]
__device__ __align__(16) __half g_w2t[32 * 128];   // W2^T fp16: [col][k]

__device__ __forceinline__ float eluf(float v) {
    return (v > 0.f) ? v : (__expf(v) - 1.f);
}
__device__ __forceinline__ unsigned int packh2(float2 v) {
    __half2 h = __floats2half2_rn(v.x, v.y);
    return *(unsigned int*)&h;
}
__device__ __forceinline__ void mma16816(float* c,
                                         unsigned a0, unsigned a1, unsigned a2, unsigned a3,
                                         unsigned b0, unsigned b1) {
    asm volatile("mma.sync.aligned.m16n8k16.row.col.f32.f16.f16.f32 "
                 "{%0,%1,%2,%3}, {%4,%5,%6,%7}, {%8,%9}, {%0,%1,%2,%3};"
                 : "+f"(c[0]), "+f"(c[1]), "+f"(c[2]), "+f"(c[3])
                 : "r"(a0), "r"(a1), "r"(a2), "r"(a3), "r"(b0), "r"(b1));
}
__device__ __forceinline__ __half2 h2shfl_xor(__half2 v, int off) {
    unsigned u = __shfl_xor_sync(FULL, *(unsigned*)&v, off);
    return *(__half2*)&u;
}
// f is (logit sum) pre-scaled by log2e; returns exp(lrelu(e)); 0 for f = -inf
__device__ __forceinline__ float wexp2(float f) {
    float m = fmaxf(f, 0.2f * f);
    float r;
    asm("ex2.approx.f32 %0, %1;" : "=f"(r) : "f"(m));
    return r;
}

// ---------------- launch 0: bucket scatter + W1T/W2T conversion ----------------
#define SCAT_BLOCKS 2000           // (EE/4 + NN) / 256
__global__ void __launch_bounds__(256) k_scatter(
        const int* __restrict__ ei,
        const float* __restrict__ W1,
        const float* __restrict__ W2) {
    int b = blockIdx.x;
    if (b < SCAT_BLOCKS) {
        int t = b * 256 + threadIdx.x;         // < 512000 = EE/4 + NN
        const int Q = EE / 4;
        if (t < Q) {
            int4 s4 = ((const int4*)ei)[t];
            int4 d4 = ((const int4*)(ei + EE))[t];
            int p;
            p = atomicAdd(&g_pos[d4.x], 1); g_csr[(d4.x << 6) + p] = s4.x;
            p = atomicAdd(&g_pos[d4.y], 1); g_csr[(d4.y << 6) + p] = s4.y;
            p = atomicAdd(&g_pos[d4.z], 1); g_csr[(d4.z << 6) + p] = s4.z;
            p = atomicAdd(&g_pos[d4.w], 1); g_csr[(d4.w << 6) + p] = s4.w;
        } else {
            int n = t - Q;                      // self loop
            int p = atomicAdd(&g_pos[n], 1);
            g_csr[(n << 6) + p] = n;
        }
        return;
    }
    int idx = (b - SCAT_BLOCKS) * 256 + threadIdx.x;   // 0..12287
    if (idx < 8192) {
        int n = idx >> 6, k = idx & 63;
        g_w1t[idx] = __float2half(W1[k * 128 + n]);
    } else {
        int j = idx - 8192;                    // 0..4095
        int col = j >> 7, k = j & 127;
        g_w2t[j] = __float2half(W2[k * 32 + col]);
    }
    if (idx == 0) {
        g_als1[4 * NN]     = NEG_INF;
        g_als1[4 * NN + 1] = NEG_INF;
        g_als1[4 * NN + 2] = NEG_INF;
        g_als1[4 * NN + 3] = NEG_INF;
        g_als2[NN] = NEG_INF;
    }
}

// ---------------- launch 1: tensor-core gemm1 (blocks < GEMM1_BLOCKS) + row pad-to-8 ----------------
#define GEMM1_BLOCKS (NN / 16)
__global__ void __launch_bounds__(128) k_gemm1pad(
        const float* __restrict__ x,
        const float* __restrict__ a_src1,
        const float* __restrict__ a_dst1) {
    if (blockIdx.x >= GEMM1_BLOCKS) {
        // pad rows to multiple of 8; store len; reset g_pos
        int n = (blockIdx.x - GEMM1_BLOCKS) * 128 + threadIdx.x;
        for (int r = 0; r < 2; r++) {
            int nn = n * 2 + r;
            if (nn < NN) {
                int p = g_pos[nn];
                g_pos[nn] = 0;
                int end = (p + 7) & ~7;
                g_len[nn] = end;
                int base = nn << 6;
                for (int i = p; i < end; i++) g_csr[base + i] = NN;
            }
        }
        return;
    }
    int n0 = blockIdx.x * 16;
    int w = threadIdx.x >> 5;
    int l = threadIdx.x & 31;
    int g = l >> 2, tg = l & 3;

    const float2* xg  = (const float2*)(x + (n0 + g) * 64);
    const float2* xg8 = (const float2*)(x + (n0 + g + 8) * 64);

    float acc[4][4];
#pragma unroll
    for (int t = 0; t < 4; t++)
#pragma unroll
        for (int i = 0; i < 4; i++) acc[t][i] = 0.f;

#pragma unroll
    for (int ks = 0; ks < 4; ks++) {
        unsigned a0 = packh2(xg [8 * ks + tg]);
        unsigned a1 = packh2(xg8[8 * ks + tg]);
        unsigned a2 = packh2(xg [8 * ks + tg + 4]);
        unsigned a3 = packh2(xg8[8 * ks + tg + 4]);
#pragma unroll
        for (int t = 0; t < 4; t++) {
            int col = 32 * w + 8 * t + g;
            unsigned b0 = *(const unsigned*)&g_w1t[col * 64 + 16 * ks + 2 * tg];
            unsigned b1 = *(const unsigned*)&g_w1t[col * 64 + 16 * ks + 2 * tg + 8];
            mma16816(acc[t], a0, a1, a2, a3, b0, b1);
        }
    }

    float psg = 0.f, psg8 = 0.f, pdg = 0.f, pdg8 = 0.f;
#pragma unroll
    for (int t = 0; t < 4; t++) {
        int c0 = 32 * w + 8 * t + 2 * tg;
        __half2 h01 = __floats2half2_rn(acc[t][0], acc[t][1]);
        __half2 h23 = __floats2half2_rn(acc[t][2], acc[t][3]);
        *(__half2*)&g_h1h[(n0 + g) * 128 + c0]     = h01;
        *(__half2*)&g_h1h[(n0 + g + 8) * 128 + c0] = h23;
        float as0 = a_src1[c0], as1 = a_src1[c0 + 1];
        float ad0 = a_dst1[c0], ad1 = a_dst1[c0 + 1];
        psg  += acc[t][0] * as0 + acc[t][1] * as1;
        psg8 += acc[t][2] * as0 + acc[t][3] * as1;
        pdg  += acc[t][0] * ad0 + acc[t][1] * ad1;
        pdg8 += acc[t][2] * ad0 + acc[t][3] * ad1;
    }
    psg  += __shfl_down_sync(FULL, psg, 2, 4);  psg  += __shfl_down_sync(FULL, psg, 1, 4);
    psg8 += __shfl_down_sync(FULL, psg8, 2, 4); psg8 += __shfl_down_sync(FULL, psg8, 1, 4);
    pdg  += __shfl_down_sync(FULL, pdg, 2, 4);  pdg  += __shfl_down_sync(FULL, pdg, 1, 4);
    pdg8 += __shfl_down_sync(FULL, pdg8, 2, 4); pdg8 += __shfl_down_sync(FULL, pdg8, 1, 4);
    if (tg == 0) {
        g_als1[(n0 + g) * 4 + w]     = psg * LOG2E;
        g_als1[(n0 + g + 8) * 4 + w] = psg8 * LOG2E;
        g_ald1[(n0 + g) * 4 + w]     = pdg * LOG2E;
        g_ald1[(n0 + g + 8) * 4 + w] = pdg8 * LOG2E;
    }
}

// ---------------- launch 2: gather1, branchless padded batches of 4 (R14-proven) ----------------
__global__ void __launch_bounds__(256) k_edge1(const float* __restrict__ b1) {
    int tid = threadIdx.x;
    int lane = tid & 31;
    int d = (blockIdx.x << 3) + (tid >> 5);
    int head = lane >> 3;

    const float2* h1v = (const float2*)g_h1h;

    float ald = g_ald1[4 * d + head];
    int beg = d << 6, end = beg + g_len[d];
    __half2 a01 = __float2half2_rn(0.f);
    __half2 a23 = __float2half2_rn(0.f);
    float den = 0.f;

    for (int j = beg; j < end; j += 4) {
        int4 s4 = *(const int4*)&g_csr[j];
        float l0 = g_als1[4 * s4.x + head];
        float l1 = g_als1[4 * s4.y + head];
        float l2 = g_als1[4 * s4.z + head];
        float l3 = g_als1[4 * s4.w + head];
        float2 r0 = h1v[(s4.x << 5) + lane];
        float2 r1 = h1v[(s4.y << 5) + lane];
        float2 r2 = h1v[(s4.z << 5) + lane];
        float2 r3 = h1v[(s4.w << 5) + lane];
        float w0 = wexp2(l0 + ald);
        float w1 = wexp2(l1 + ald);
        float w2 = wexp2(l2 + ald);
        float w3 = wexp2(l3 + ald);
        den += (w0 + w1) + (w2 + w3);
        __half2 h0 = __float2half2_rn(w0);
        __half2 h1w = __float2half2_rn(w1);
        __half2 h2w = __float2half2_rn(w2);
        __half2 h3w = __float2half2_rn(w3);
        a01 = __hfma2(*(__half2*)&r0.x, h0, a01);
        a23 = __hfma2(*(__half2*)&r0.y, h0, a23);
        a01 = __hfma2(*(__half2*)&r1.x, h1w, a01);
        a23 = __hfma2(*(__half2*)&r1.y, h1w, a23);
        a01 = __hfma2(*(__half2*)&r2.x, h2w, a01);
        a23 = __hfma2(*(__half2*)&r2.y, h2w, a23);
        a01 = __hfma2(*(__half2*)&r3.x, h3w, a01);
        a23 = __hfma2(*(__half2*)&r3.y, h3w, a23);
    }

    float inv = 1.f / den;
    float4 bb = *(const float4*)&b1[lane * 4];
    float2 f01 = __half22float2(a01);
    float2 f23 = __half22float2(a23);
    __half2 p0 = __floats2half2_rn(eluf(f01.x * inv + bb.x), eluf(f01.y * inv + bb.y));
    __half2 p1 = __floats2half2_rn(eluf(f23.x * inv + bb.z), eluf(f23.y * inv + bb.w));
    uint2 st;
    st.x = *(unsigned int*)&p0;
    st.y = *(unsigned int*)&p1;
    ((uint2*)g_act)[(d << 5) + lane] = st;
}

// ---------------- launch 3 (PROFILED): tensor-core gemm2 + scaled logits2 ----------------
__global__ void __launch_bounds__(128) k_gemm2(const float* __restrict__ a2s,
                                               const float* __restrict__ a2d) {
    int w = threadIdx.x >> 5;
    int l = threadIdx.x & 31;
    int g = l >> 2, tg = l & 3;
    int n0 = blockIdx.x * 64 + w * 16;

    const __half* act0 = &g_act[(n0 + g) * 128];
    const __half* act8 = &g_act[(n0 + g + 8) * 128];

    float acc[4][4];
#pragma unroll
    for (int t = 0; t < 4; t++)
#pragma unroll
        for (int i = 0; i < 4; i++) acc[t][i] = 0.f;

#pragma unroll
    for (int ks = 0; ks < 8; ks++) {
        unsigned a0 = *(const unsigned*)&act0[16 * ks + 2 * tg];
        unsigned a1 = *(const unsigned*)&act8[16 * ks + 2 * tg];
        unsigned a2 = *(const unsigned*)&act0[16 * ks + 8 + 2 * tg];
        unsigned a3 = *(const unsigned*)&act8[16 * ks + 8 + 2 * tg];
#pragma unroll
        for (int t = 0; t < 4; t++) {
            int col = 8 * t + g;
            unsigned b0 = *(const unsigned*)&g_w2t[col * 128 + 16 * ks + 2 * tg];
            unsigned b1 = *(const unsigned*)&g_w2t[col * 128 + 16 * ks + 2 * tg + 8];
            mma16816(acc[t], a0, a1, a2, a3, b0, b1);
        }
    }

    float psg = 0.f, psg8 = 0.f, pdg = 0.f, pdg8 = 0.f;
#pragma unroll
    for (int t = 0; t < 4; t++) {
        int c0 = 8 * t + 2 * tg;
        __half2 h01 = __floats2half2_rn(acc[t][0], acc[t][1]);
        __half2 h23 = __floats2half2_rn(acc[t][2], acc[t][3]);
        *(__half2*)&g_h2h[(n0 + g) * 32 + c0]     = h01;
        *(__half2*)&g_h2h[(n0 + g + 8) * 32 + c0] = h23;
        float as0 = a2s[c0], as1 = a2s[c0 + 1];
        float ad0 = a2d[c0], ad1 = a2d[c0 + 1];
        psg  += acc[t][0] * as0 + acc[t][1] * as1;
        psg8 += acc[t][2] * as0 + acc[t][3] * as1;
        pdg  += acc[t][0] * ad0 + acc[t][1] * ad1;
        pdg8 += acc[t][2] * ad0 + acc[t][3] * ad1;
    }
    psg  += __shfl_down_sync(FULL, psg, 2, 4);  psg  += __shfl_down_sync(FULL, psg, 1, 4);
    psg8 += __shfl_down_sync(FULL, psg8, 2, 4); psg8 += __shfl_down_sync(FULL, psg8, 1, 4);
    pdg  += __shfl_down_sync(FULL, pdg, 2, 4);  pdg  += __shfl_down_sync(FULL, pdg, 1, 4);
    pdg8 += __shfl_down_sync(FULL, pdg8, 2, 4); pdg8 += __shfl_down_sync(FULL, pdg8, 1, 4);
    if (tg == 0) {
        g_als2[n0 + g]      = psg * LOG2E;
        g_als2[n0 + g + 8]  = psg8 * LOG2E;
        g_ald2[n0 + g]      = pdg * LOG2E;
        g_ald2[n0 + g + 8]  = pdg8 * LOG2E;
    }
}

// ---------------- launch 4: gather2, batch-8 (half-warp x int4), branchless ----------------
// warp per node; slot = lane>>4 handles 4 edges via one int4; 8 edges in flight.
__global__ void __launch_bounds__(256) k_edge2(const float* __restrict__ b2) {
    int lane = threadIdx.x & 31;
    int d = (blockIdx.x << 3) + (threadIdx.x >> 5);
    int slot = lane >> 4;          // 0/1
    int c = lane & 15;             // half2 column index (32 halves = 16 half2)
    float ald = g_ald2[d];
    int beg = d << 6, end = beg + g_len[d];     // len multiple of 8
    const __half2* rows = (const __half2*)g_h2h;
    __half2 acc = __float2half2_rn(0.f);
    float den = 0.f;
    for (int j = beg; j < end; j += 8) {
        int4 s4 = *(const int4*)&g_csr[j + 4 * slot];
        float l0 = g_als2[s4.x];
        float l1 = g_als2[s4.y];
        float l2 = g_als2[s4.z];
        float l3 = g_als2[s4.w];
        __half2 v0 = rows[(s4.x << 4) + c];
        __half2 v1 = rows[(s4.y << 4) + c];
        __half2 v2 = rows[(s4.z << 4) + c];
        __half2 v3 = rows[(s4.w << 4) + c];
        float w0 = wexp2(l0 + ald);
        float w1 = wexp2(l1 + ald);
        float w2 = wexp2(l2 + ald);
        float w3 = wexp2(l3 + ald);
        den += (w0 + w1) + (w2 + w3);
        acc = __hfma2(v0, __float2half2_rn(w0), acc);
        acc = __hfma2(v1, __float2half2_rn(w1), acc);
        acc = __hfma2(v2, __float2half2_rn(w2), acc);
        acc = __hfma2(v3, __float2half2_rn(w3), acc);
    }
    den += __shfl_xor_sync(FULL, den, 16);
    acc = __hadd2(acc, h2shfl_xor(acc, 16));
    if (slot == 0) {
        float inv = 1.f / den;
        float2 f = __half22float2(acc);
        int c2 = c << 1;
        float vx = eluf(f.x * inv + b2[c2]);
        float vy = eluf(f.y * inv + b2[c2 + 1]);
        int g = d / 400;
        atomicAdd(&g_pool[g * 32 + c2], vx);
        atomicAdd(&g_pool[g * 32 + c2 + 1], vy);
    }
}

// ---------------- launch 5: classifier MLP (resets g_pool) ----------------
__global__ void k_mlp(const float* __restrict__ clinical,
                      const float* __restrict__ Wc1,
                      const float* __restrict__ bc1,
                      const float* __restrict__ Wc2,
                      const float* __restrict__ bc2,
                      float* __restrict__ out) {
    int g = blockIdx.x;
    int t = threadIdx.x;
    __shared__ float sf[37];
    __shared__ float sz[16];
    if (t < 32) {
        sf[t] = g_pool[g * 32 + t] * (1.f / 400.f);
        g_pool[g * 32 + t] = 0.f;
    } else if (t < 37) {
        sf[t] = clinical[g * 5 + (t - 32)];
    }
    __syncthreads();
    if (t < 16) {
        float z = bc1[t];
#pragma unroll
        for (int i = 0; i < 37; i++) z += sf[i] * Wc1[i * 16 + t];
        sz[t] = eluf(z);
    }
    __syncthreads();
    if (t == 0) {
        float o = bc2[0];
#pragma unroll
        for (int j = 0; j < 16; j++) o += sz[j] * Wc2[j];
        out[g] = o;
    }
}

// ---------------- launch ----------------
extern "C" void kernel_launch(void* const* d_in, const int* in_sizes, int n_in,
                              void* d_out, int out_size) {
    const float* x        = (const float*)d_in[0];
    const int*   ei       = (const int*)d_in[1];
    const float* clinical = (const float*)d_in[3];
    const float* W1       = (const float*)d_in[4];
    const float* a_src1   = (const float*)d_in[5];
    const float* a_dst1   = (const float*)d_in[6];
    const float* b1       = (const float*)d_in[7];
    const float* W2       = (const float*)d_in[8];
    const float* a_src2   = (const float*)d_in[9];
    const float* a_dst2   = (const float*)d_in[10];
    const float* b2       = (const float*)d_in[11];
    const float* Wc1      = (const float*)d_in[12];
    const float* bc1      = (const float*)d_in[13];
    const float* Wc2      = (const float*)d_in[14];
    const float* bc2      = (const float*)d_in[15];
    float* out = (float*)d_out;

    k_scatter<<<SCAT_BLOCKS + 48, 256>>>(ei, W1, W2);
    k_gemm1pad<<<GEMM1_BLOCKS + NN / 256, 128>>>(x, a_src1, a_dst1);
    k_edge1<<<NN / 8, 256>>>(b1);
    k_gemm2<<<NN / 64, 128>>>(a_src2, a_dst2);          // idx 3 -> profiled
    k_edge2<<<NN / 8, 256>>>(b2);
    k_mlp<<<GG, 64>>>(clinical, Wc1, bc1, Wc2, bc2, out);
}

// round 17
// speedup vs baseline: 1.1472x; 1.0819x over previous
#include <cuda_runtime.h>
#include <cuda_fp16.h>

#define NN 102400
#define EE 1638400
#define SLOTS 64                  // fixed CSR row capacity (P(overflow) ~ 1e-15)
#define GG 256
#define FULL 0xffffffffu
#define NEG_INF __int_as_float(0xff800000)
#define LOG2E 1.4426950408889634f

// ---------------- scratch (device globals; no allocation) ----------------
// Invariant: g_pos and g_pool are ZERO at entry of every kernel_launch call.
// Rows NN of g_h1h / g_h2h are NEVER written -> remain zero (dummy pad node).
// All logits are stored PRE-SCALED by log2(e).
__device__ __align__(16) __half g_h1h[(NN + 1) * 128];
__device__ __align__(16) float  g_als1[(NN + 1) * 4];
__device__ __align__(16) float  g_ald1[NN * 4];
__device__ __align__(16) __half g_act[NN * 128];
__device__ __align__(16) __half g_h2h[(NN + 1) * 32];
__device__ __align__(16) float  g_als2[NN + 1];
__device__ __align__(16) float  g_ald2[NN];
__device__ __align__(16) int    g_pos[NN];
__device__ __align__(16) int    g_len[NN];
__device__ __align__(16) int    g_csr[NN * SLOTS];
__device__ __align__(16) float  g_pool[GG * 32];
__device__ __align__(16) __half g_w1t[128 * 64];   // W1^T fp16: [col][k]
__device__ __align__(16) __half g_w2t[32 * 128];   // W2^T fp16: [col][k]

__device__ __forceinline__ float eluf(float v) {
    return (v > 0.f) ? v : (__expf(v) - 1.f);
}
__device__ __forceinline__ unsigned int packh2(float2 v) {
    __half2 h = __floats2half2_rn(v.x, v.y);
    return *(unsigned int*)&h;
}
__device__ __forceinline__ void mma16816(float* c,
                                         unsigned a0, unsigned a1, unsigned a2, unsigned a3,
                                         unsigned b0, unsigned b1) {
    asm volatile("mma.sync.aligned.m16n8k16.row.col.f32.f16.f16.f32 "
                 "{%0,%1,%2,%3}, {%4,%5,%6,%7}, {%8,%9}, {%0,%1,%2,%3};"
                 : "+f"(c[0]), "+f"(c[1]), "+f"(c[2]), "+f"(c[3])
                 : "r"(a0), "r"(a1), "r"(a2), "r"(a3), "r"(b0), "r"(b1));
}
__device__ __forceinline__ __half2 h2shfl_xor(__half2 v, int off) {
    unsigned u = __shfl_xor_sync(FULL, *(unsigned*)&v, off);
    return *(__half2*)&u;
}
// f is (logit sum) pre-scaled by log2e; returns exp(lrelu(e)); 0 for f = -inf
__device__ __forceinline__ float wexp2(float f) {
    float m = fmaxf(f, 0.2f * f);
    float r;
    asm("ex2.approx.f32 %0, %1;" : "=f"(r) : "f"(m));
    return r;
}

// ---------------- launch 0: bucket scatter + W1T/W2T conversion ----------------
#define SCAT_BLOCKS 2000           // (EE/4 + NN) / 256
__global__ void __launch_bounds__(256) k_scatter(
        const int* __restrict__ ei,
        const float* __restrict__ W1,
        const float* __restrict__ W2) {
    int b = blockIdx.x;
    if (b < SCAT_BLOCKS) {
        int t = b * 256 + threadIdx.x;         // < 512000 = EE/4 + NN
        const int Q = EE / 4;
        if (t < Q) {
            int4 s4 = ((const int4*)ei)[t];
            int4 d4 = ((const int4*)(ei + EE))[t];
            int p;
            p = atomicAdd(&g_pos[d4.x], 1); g_csr[(d4.x << 6) + p] = s4.x;
            p = atomicAdd(&g_pos[d4.y], 1); g_csr[(d4.y << 6) + p] = s4.y;
            p = atomicAdd(&g_pos[d4.z], 1); g_csr[(d4.z << 6) + p] = s4.z;
            p = atomicAdd(&g_pos[d4.w], 1); g_csr[(d4.w << 6) + p] = s4.w;
        } else {
            int n = t - Q;                      // self loop
            int p = atomicAdd(&g_pos[n], 1);
            g_csr[(n << 6) + p] = n;
        }
        return;
    }
    int idx = (b - SCAT_BLOCKS) * 256 + threadIdx.x;   // 0..12287
    if (idx < 8192) {
        int n = idx >> 6, k = idx & 63;
        g_w1t[idx] = __float2half(W1[k * 128 + n]);
    } else {
        int j = idx - 8192;                    // 0..4095
        int col = j >> 7, k = j & 127;
        g_w2t[j] = __float2half(W2[k * 32 + col]);
    }
    if (idx == 0) {
        g_als1[4 * NN]     = NEG_INF;
        g_als1[4 * NN + 1] = NEG_INF;
        g_als1[4 * NN + 2] = NEG_INF;
        g_als1[4 * NN + 3] = NEG_INF;
        g_als2[NN] = NEG_INF;
    }
}

// ---------------- launch 1: tensor-core gemm1 (blocks < GEMM1_BLOCKS) + row pad-to-4 ----------------
#define GEMM1_BLOCKS (NN / 16)
__global__ void __launch_bounds__(128) k_gemm1pad(
        const float* __restrict__ x,
        const float* __restrict__ a_src1,
        const float* __restrict__ a_dst1) {
    if (blockIdx.x >= GEMM1_BLOCKS) {
        // pad rows to multiple of 4; store len; reset g_pos
        int n = (blockIdx.x - GEMM1_BLOCKS) * 128 + threadIdx.x;
        for (int r = 0; r < 2; r++) {
            int nn = n * 2 + r;
            if (nn < NN) {
                int p = g_pos[nn];
                g_pos[nn] = 0;
                int end = (p + 3) & ~3;
                g_len[nn] = end;
                int base = nn << 6;
                for (int i = p; i < end; i++) g_csr[base + i] = NN;
            }
        }
        return;
    }
    int n0 = blockIdx.x * 16;
    int w = threadIdx.x >> 5;
    int l = threadIdx.x & 31;
    int g = l >> 2, tg = l & 3;

    const float2* xg  = (const float2*)(x + (n0 + g) * 64);
    const float2* xg8 = (const float2*)(x + (n0 + g + 8) * 64);

    float acc[4][4];
#pragma unroll
    for (int t = 0; t < 4; t++)
#pragma unroll
        for (int i = 0; i < 4; i++) acc[t][i] = 0.f;

#pragma unroll
    for (int ks = 0; ks < 4; ks++) {
        unsigned a0 = packh2(xg [8 * ks + tg]);
        unsigned a1 = packh2(xg8[8 * ks + tg]);
        unsigned a2 = packh2(xg [8 * ks + tg + 4]);
        unsigned a3 = packh2(xg8[8 * ks + tg + 4]);
#pragma unroll
        for (int t = 0; t < 4; t++) {
            int col = 32 * w + 8 * t + g;
            unsigned b0 = *(const unsigned*)&g_w1t[col * 64 + 16 * ks + 2 * tg];
            unsigned b1 = *(const unsigned*)&g_w1t[col * 64 + 16 * ks + 2 * tg + 8];
            mma16816(acc[t], a0, a1, a2, a3, b0, b1);
        }
    }

    float psg = 0.f, psg8 = 0.f, pdg = 0.f, pdg8 = 0.f;
#pragma unroll
    for (int t = 0; t < 4; t++) {
        int c0 = 32 * w + 8 * t + 2 * tg;
        __half2 h01 = __floats2half2_rn(acc[t][0], acc[t][1]);
        __half2 h23 = __floats2half2_rn(acc[t][2], acc[t][3]);
        *(__half2*)&g_h1h[(n0 + g) * 128 + c0]     = h01;
        *(__half2*)&g_h1h[(n0 + g + 8) * 128 + c0] = h23;
        float as0 = a_src1[c0], as1 = a_src1[c0 + 1];
        float ad0 = a_dst1[c0], ad1 = a_dst1[c0 + 1];
        psg  += acc[t][0] * as0 + acc[t][1] * as1;
        psg8 += acc[t][2] * as0 + acc[t][3] * as1;
        pdg  += acc[t][0] * ad0 + acc[t][1] * ad1;
        pdg8 += acc[t][2] * ad0 + acc[t][3] * ad1;
    }
    psg  += __shfl_down_sync(FULL, psg, 2, 4);  psg  += __shfl_down_sync(FULL, psg, 1, 4);
    psg8 += __shfl_down_sync(FULL, psg8, 2, 4); psg8 += __shfl_down_sync(FULL, psg8, 1, 4);
    pdg  += __shfl_down_sync(FULL, pdg, 2, 4);  pdg  += __shfl_down_sync(FULL, pdg, 1, 4);
    pdg8 += __shfl_down_sync(FULL, pdg8, 2, 4); pdg8 += __shfl_down_sync(FULL, pdg8, 1, 4);
    if (tg == 0) {
        g_als1[(n0 + g) * 4 + w]     = psg * LOG2E;
        g_als1[(n0 + g + 8) * 4 + w] = psg8 * LOG2E;
        g_ald1[(n0 + g) * 4 + w]     = pdg * LOG2E;
        g_ald1[(n0 + g + 8) * 4 + w] = pdg8 * LOG2E;
    }
}

// ---------------- launch 2: gather1, branchless padded batches of 4 (R14-proven) ----------------
__global__ void __launch_bounds__(256) k_edge1(const float* __restrict__ b1) {
    int tid = threadIdx.x;
    int lane = tid & 31;
    int d = (blockIdx.x << 3) + (tid >> 5);
    int head = lane >> 3;

    const float2* h1v = (const float2*)g_h1h;

    float ald = g_ald1[4 * d + head];
    int beg = d << 6, end = beg + g_len[d];
    __half2 a01 = __float2half2_rn(0.f);
    __half2 a23 = __float2half2_rn(0.f);
    float den = 0.f;

    for (int j = beg; j < end; j += 4) {
        int4 s4 = *(const int4*)&g_csr[j];
        float l0 = g_als1[4 * s4.x + head];
        float l1 = g_als1[4 * s4.y + head];
        float l2 = g_als1[4 * s4.z + head];
        float l3 = g_als1[4 * s4.w + head];
        float2 r0 = h1v[(s4.x << 5) + lane];
        float2 r1 = h1v[(s4.y << 5) + lane];
        float2 r2 = h1v[(s4.z << 5) + lane];
        float2 r3 = h1v[(s4.w << 5) + lane];
        float w0 = wexp2(l0 + ald);
        float w1 = wexp2(l1 + ald);
        float w2 = wexp2(l2 + ald);
        float w3 = wexp2(l3 + ald);
        den += (w0 + w1) + (w2 + w3);
        __half2 h0 = __float2half2_rn(w0);
        __half2 h1w = __float2half2_rn(w1);
        __half2 h2w = __float2half2_rn(w2);
        __half2 h3w = __float2half2_rn(w3);
        a01 = __hfma2(*(__half2*)&r0.x, h0, a01);
        a23 = __hfma2(*(__half2*)&r0.y, h0, a23);
        a01 = __hfma2(*(__half2*)&r1.x, h1w, a01);
        a23 = __hfma2(*(__half2*)&r1.y, h1w, a23);
        a01 = __hfma2(*(__half2*)&r2.x, h2w, a01);
        a23 = __hfma2(*(__half2*)&r2.y, h2w, a23);
        a01 = __hfma2(*(__half2*)&r3.x, h3w, a01);
        a23 = __hfma2(*(__half2*)&r3.y, h3w, a23);
    }

    float inv = 1.f / den;
    float4 bb = *(const float4*)&b1[lane * 4];
    float2 f01 = __half22float2(a01);
    float2 f23 = __half22float2(a23);
    __half2 p0 = __floats2half2_rn(eluf(f01.x * inv + bb.x), eluf(f01.y * inv + bb.y));
    __half2 p1 = __floats2half2_rn(eluf(f23.x * inv + bb.z), eluf(f23.y * inv + bb.w));
    uint2 st;
    st.x = *(unsigned int*)&p0;
    st.y = *(unsigned int*)&p1;
    ((uint2*)g_act)[(d << 5) + lane] = st;
}

// ---------------- launch 3 (PROFILED): gemm2 with SMEM-staged act ----------------
// block = 128 thr = 4 warps; block covers 64 nodes. act staged coalesced into
// shared with 8-half row padding (stride 272 B) -> conflict-free fragment reads.
__global__ void __launch_bounds__(128) k_gemm2(const float* __restrict__ a2s,
                                               const float* __restrict__ a2d) {
    __shared__ __align__(16) __half act_s[64][136];   // 128 + 8 pad
    int tid = threadIdx.x;
    int nb = blockIdx.x * 64;

    // stage 64 rows x 128 halves (16 KB), coalesced uint4 loads
    const uint4* src = (const uint4*)&g_act[nb * 128];
#pragma unroll
    for (int it = 0; it < 8; it++) {
        int idx = it * 128 + tid;              // 1024 uint4 total; 16 per row
        int node = idx >> 4, c8 = idx & 15;
        uint4 v = src[idx];
        *(uint4*)&act_s[node][c8 * 8] = v;
    }
    __syncthreads();

    int w = tid >> 5;
    int l = tid & 31;
    int g = l >> 2, tg = l & 3;
    int n0 = nb + w * 16;
    const __half* act0 = act_s[w * 16 + g];
    const __half* act8 = act_s[w * 16 + g + 8];

    float acc[4][4];
#pragma unroll
    for (int t = 0; t < 4; t++)
#pragma unroll
        for (int i = 0; i < 4; i++) acc[t][i] = 0.f;

#pragma unroll
    for (int ks = 0; ks < 8; ks++) {
        unsigned a0 = *(const unsigned*)&act0[16 * ks + 2 * tg];
        unsigned a1 = *(const unsigned*)&act8[16 * ks + 2 * tg];
        unsigned a2 = *(const unsigned*)&act0[16 * ks + 8 + 2 * tg];
        unsigned a3 = *(const unsigned*)&act8[16 * ks + 8 + 2 * tg];
#pragma unroll
        for (int t = 0; t < 4; t++) {
            int col = 8 * t + g;
            unsigned b0 = *(const unsigned*)&g_w2t[col * 128 + 16 * ks + 2 * tg];
            unsigned b1 = *(const unsigned*)&g_w2t[col * 128 + 16 * ks + 2 * tg + 8];
            mma16816(acc[t], a0, a1, a2, a3, b0, b1);
        }
    }

    float psg = 0.f, psg8 = 0.f, pdg = 0.f, pdg8 = 0.f;
#pragma unroll
    for (int t = 0; t < 4; t++) {
        int c0 = 8 * t + 2 * tg;
        __half2 h01 = __floats2half2_rn(acc[t][0], acc[t][1]);
        __half2 h23 = __floats2half2_rn(acc[t][2], acc[t][3]);
        *(__half2*)&g_h2h[(n0 + g) * 32 + c0]     = h01;
        *(__half2*)&g_h2h[(n0 + g + 8) * 32 + c0] = h23;
        float as0 = a2s[c0], as1 = a2s[c0 + 1];
        float ad0 = a2d[c0], ad1 = a2d[c0 + 1];
        psg  += acc[t][0] * as0 + acc[t][1] * as1;
        psg8 += acc[t][2] * as0 + acc[t][3] * as1;
        pdg  += acc[t][0] * ad0 + acc[t][1] * ad1;
        pdg8 += acc[t][2] * ad0 + acc[t][3] * ad1;
    }
    psg  += __shfl_down_sync(FULL, psg, 2, 4);  psg  += __shfl_down_sync(FULL, psg, 1, 4);
    psg8 += __shfl_down_sync(FULL, psg8, 2, 4); psg8 += __shfl_down_sync(FULL, psg8, 1, 4);
    pdg  += __shfl_down_sync(FULL, pdg, 2, 4);  pdg  += __shfl_down_sync(FULL, pdg, 1, 4);
    pdg8 += __shfl_down_sync(FULL, pdg8, 2, 4); pdg8 += __shfl_down_sync(FULL, pdg8, 1, 4);
    if (tg == 0) {
        g_als2[n0 + g]      = psg * LOG2E;
        g_als2[n0 + g + 8]  = psg8 * LOG2E;
        g_ald2[n0 + g]      = pdg * LOG2E;
        g_ald2[n0 + g + 8]  = pdg8 * LOG2E;
    }
}

// ---------------- launch 4: gather2, batch-4 (R14 structure, uniform int4 csr load) ----------------
__global__ void __launch_bounds__(256) k_edge2(const float* __restrict__ b2) {
    int lane = threadIdx.x & 31;
    int d = (blockIdx.x << 3) + (threadIdx.x >> 5);
    int hw = lane >> 4;
    int c2 = (lane & 15) << 1;
    float ald = g_ald2[d];
    int beg = d << 6, end = beg + g_len[d];    // len multiple of 4
    __half2 acc = __float2half2_rn(0.f);
    float den = 0.f;
    for (int j = beg; j < end; j += 4) {
        int4 s4 = *(const int4*)&g_csr[j];     // warp-uniform LDG.128
        int sa = hw ? s4.z : s4.x;
        int sb = hw ? s4.w : s4.y;
        float la = g_als2[sa];
        float lb = g_als2[sb];
        __half2 va = *(const __half2*)(g_h2h + sa * 32 + c2);
        __half2 vb = *(const __half2*)(g_h2h + sb * 32 + c2);
        float wa = wexp2(la + ald);
        float wb = wexp2(lb + ald);
        den += wa + wb;
        acc = __hfma2(va, __float2half2_rn(wa), acc);
        acc = __hfma2(vb, __float2half2_rn(wb), acc);
    }
    den += __shfl_xor_sync(FULL, den, 16);
    acc = __hadd2(acc, h2shfl_xor(acc, 16));
    if (hw == 0) {
        float inv = 1.f / den;
        float2 f = __half22float2(acc);
        float vx = eluf(f.x * inv + b2[c2]);
        float vy = eluf(f.y * inv + b2[c2 + 1]);
        int g = d / 400;
        atomicAdd(&g_pool[g * 32 + c2], vx);
        atomicAdd(&g_pool[g * 32 + c2 + 1], vy);
    }
}

// ---------------- launch 5: classifier MLP (resets g_pool) ----------------
__global__ void k_mlp(const float* __restrict__ clinical,
                      const float* __restrict__ Wc1,
                      const float* __restrict__ bc1,
                      const float* __restrict__ Wc2,
                      const float* __restrict__ bc2,
                      float* __restrict__ out) {
    int g = blockIdx.x;
    int t = threadIdx.x;
    __shared__ float sf[37];
    __shared__ float sz[16];
    if (t < 32) {
        sf[t] = g_pool[g * 32 + t] * (1.f / 400.f);
        g_pool[g * 32 + t] = 0.f;
    } else if (t < 37) {
        sf[t] = clinical[g * 5 + (t - 32)];
    }
    __syncthreads();
    if (t < 16) {
        float z = bc1[t];
#pragma unroll
        for (int i = 0; i < 37; i++) z += sf[i] * Wc1[i * 16 + t];
        sz[t] = eluf(z);
    }
    __syncthreads();
    if (t == 0) {
        float o = bc2[0];
#pragma unroll
        for (int j = 0; j < 16; j++) o += sz[j] * Wc2[j];
        out[g] = o;
    }
}

// ---------------- launch ----------------
extern "C" void kernel_launch(void* const* d_in, const int* in_sizes, int n_in,
                              void* d_out, int out_size) {
    const float* x        = (const float*)d_in[0];
    const int*   ei       = (const int*)d_in[1];
    const float* clinical = (const float*)d_in[3];
    const float* W1       = (const float*)d_in[4];
    const float* a_src1   = (const float*)d_in[5];
    const float* a_dst1   = (const float*)d_in[6];
    const float* b1       = (const float*)d_in[7];
    const float* W2       = (const float*)d_in[8];
    const float* a_src2   = (const float*)d_in[9];
    const float* a_dst2   = (const float*)d_in[10];
    const float* b2       = (const float*)d_in[11];
    const float* Wc1      = (const float*)d_in[12];
    const float* bc1      = (const float*)d_in[13];
    const float* Wc2      = (const float*)d_in[14];
    const float* bc2      = (const float*)d_in[15];
    float* out = (float*)d_out;

    k_scatter<<<SCAT_BLOCKS + 48, 256>>>(ei, W1, W2);
    k_gemm1pad<<<GEMM1_BLOCKS + NN / 256, 128>>>(x, a_src1, a_dst1);
    k_edge1<<<NN / 8, 256>>>(b1);
    k_gemm2<<<NN / 64, 128>>>(a_src2, a_dst2);          // idx 3 -> profiled
    k_edge2<<<NN / 8, 256>>>(b2);
    k_mlp<<<GG, 64>>>(clinical, Wc1, bc1, Wc2, bc2, out);
}